// round 8
// baseline (speedup 1.0000x reference)
#include <cuda_runtime.h>
#include <float.h>

#define Bn 4
#define Nn 16384
#define Sn 4096
#define Cin 256
#define Cout 256

#define SPLITS 8
#define SCHUNK (Sn / SPLITS)   // 512 candidates per CTA

typedef unsigned long long u64;

__device__ __forceinline__ u64 pack2(float x, float y) {
    u64 r; asm("mov.b64 %0, {%1,%2};" : "=l"(r) : "f"(x), "f"(y)); return r;
}
__device__ __forceinline__ void unpack2(u64 v, float& x, float& y) {
    asm("mov.b64 {%0,%1}, %2;" : "=f"(x), "=f"(y) : "l"(v));
}
__device__ __forceinline__ u64 ffma2(u64 a, u64 b, u64 c) {
    u64 d; asm("fma.rn.f32x2 %0, %1, %2, %3;" : "=l"(d) : "l"(a), "l"(b), "l"(c)); return d;
}

// Scratch (device globals -- allocation-free per harness rules)
__device__ float g_G[Bn * Sn * Cout];            // [b][s][o], 16.8 MB
__device__ float g_w[Bn * Nn * 3];               // final interp weights
__device__ int   g_i[Bn * Nn * 3];               // final neighbor indices
__device__ float g_pd[SPLITS * Bn * Nn * 3];     // partial top-3 rank values
__device__ int   g_pi[SPLITS * Bn * Nn * 3];     // partial top-3 indices

// ---------------------------------------------------------------------------
// K1: G[b][s][o] = sum_c P[b][c][s] * W[o][c] + bias[o]
// (Measured 58us -- unchanged.)
// ---------------------------------------------------------------------------
__global__ __launch_bounds__(256, 2) void k1_gemm(const float* __restrict__ P,
                                                  const float* __restrict__ W,
                                                  const float* __restrict__ bias) {
    __shared__ float sP[2][8][128];
    __shared__ float sW[2][8][128];

    const int b  = blockIdx.z;
    const int s0 = blockIdx.x * 128;
    const int o0 = blockIdx.y * 128;
    const int tid = threadIdx.x;
    const int txo = tid & 15;
    const int tys = tid >> 4;
    const int obase = txo * 8;
    const int sbase = tys * 8;

    const float* Pb = P + b * Cin * Sn;

    const int lk  = tid >> 5;
    const int ls4 = (tid & 31) * 4;
    const int wo  = tid >> 1;
    const int wk  = (tid & 1) * 4;

    u64 acc[8][4];
#pragma unroll
    for (int i = 0; i < 8; i++)
#pragma unroll
        for (int j = 0; j < 4; j++) acc[i][j] = 0ull;

    float4 pA = *(const float4*)&Pb[lk * Sn + s0 + ls4];
    float4 pW = *(const float4*)&W[(o0 + wo) * Cin + wk];
    *(float4*)&sP[0][lk][ls4] = pA;
    sW[0][wk + 0][wo] = pW.x;
    sW[0][wk + 1][wo] = pW.y;
    sW[0][wk + 2][wo] = pW.z;
    sW[0][wk + 3][wo] = pW.w;
    __syncthreads();

    for (int step = 0; step < 32; step++) {
        const int cur = step & 1;
        const int nxt = cur ^ 1;
        if (step < 31) {
            const int k0 = (step + 1) * 8;
            pA = *(const float4*)&Pb[(k0 + lk) * Sn + s0 + ls4];
            pW = *(const float4*)&W[(o0 + wo) * Cin + k0 + wk];
        }

#pragma unroll
        for (int k = 0; k < 8; k++) {
            const ulonglong2 w01 = *(const ulonglong2*)&sW[cur][k][obase];
            const ulonglong2 w23 = *(const ulonglong2*)&sW[cur][k][obase + 4];
            const float4 a0 = *(const float4*)&sP[cur][k][sbase];
            const float4 a1 = *(const float4*)&sP[cur][k][sbase + 4];
            const u64 ad[8] = {pack2(a0.x, a0.x), pack2(a0.y, a0.y),
                               pack2(a0.z, a0.z), pack2(a0.w, a0.w),
                               pack2(a1.x, a1.x), pack2(a1.y, a1.y),
                               pack2(a1.z, a1.z), pack2(a1.w, a1.w)};
            const u64 wv[4] = {w01.x, w01.y, w23.x, w23.y};
#pragma unroll
            for (int i = 0; i < 8; i++)
#pragma unroll
                for (int j = 0; j < 4; j++)
                    acc[i][j] = ffma2(ad[i], wv[j], acc[i][j]);
        }

        if (step < 31) {
            *(float4*)&sP[nxt][lk][ls4] = pA;
            sW[nxt][wk + 0][wo] = pW.x;
            sW[nxt][wk + 1][wo] = pW.y;
            sW[nxt][wk + 2][wo] = pW.z;
            sW[nxt][wk + 3][wo] = pW.w;
        }
        __syncthreads();
    }

    float* Gb = g_G + b * Sn * Cout;
    const float4 bb0 = *(const float4*)&bias[o0 + obase];
    const float4 bb1 = *(const float4*)&bias[o0 + obase + 4];
#pragma unroll
    for (int i = 0; i < 8; i++) {
        const float2 p0 = *(float2*)&acc[i][0];
        const float2 p1 = *(float2*)&acc[i][1];
        const float2 p2 = *(float2*)&acc[i][2];
        const float2 p3 = *(float2*)&acc[i][3];
        float4 v0, v1;
        v0.x = p0.x + bb0.x; v0.y = p0.y + bb0.y;
        v0.z = p1.x + bb0.z; v0.w = p1.y + bb0.w;
        v1.x = p2.x + bb1.x; v1.y = p2.y + bb1.y;
        v1.z = p3.x + bb1.z; v1.w = p3.y + bb1.w;
        float* row = &Gb[(s0 + sbase + i) * Cout + o0 + obase];
        *(float4*)&row[0] = v0;
        *(float4*)&row[4] = v1;
    }
}

// ---------------------------------------------------------------------------
// K2a: partial 3-NN over one S-chunk. 256 threads x 4 points/thread.
// Candidate table duplicated ({x,x},{y,y},{z,z},{w,w}) so one ffma2 chain
// scores 2 points. Grid (16, 8, 4) = 512 CTAs.
// ---------------------------------------------------------------------------
struct QEnt { ulonglong2 a; ulonglong2 b; };   // a={x2,y2}, b={z2,w2}

__global__ __launch_bounds__(256) void k2_partial(const float* __restrict__ xyz1,
                                                  const float* __restrict__ xyz2) {
    __shared__ QEnt qtab[SCHUNK];   // 16 KB

    const int b   = blockIdx.z;
    const int sp  = blockIdx.y;
    const int n0  = blockIdx.x * 1024;
    const int tid = threadIdx.x;
    const int sb  = sp * SCHUNK;

    const float* x2 = xyz2 + b * 3 * Sn;
    for (int s = tid; s < SCHUNK; s += 256) {
        const float x = x2[sb + s];
        const float y = x2[Sn + sb + s];
        const float z = x2[2 * Sn + sb + s];
        const float w = x * x + y * y + z * z;
        QEnt q;
        q.a.x = pack2(-2.f * x, -2.f * x);
        q.a.y = pack2(-2.f * y, -2.f * y);
        q.b.x = pack2(-2.f * z, -2.f * z);
        q.b.y = pack2(w, w);
        qtab[s] = q;
    }
    __syncthreads();

    const float* x1 = xyz1 + b * 3 * Nn;
    const int nA = n0 + tid;
    const int nB = nA + 256;
    const int nC = nA + 512;
    const int nD = nA + 768;

    const float pxA = x1[nA], pyA = x1[Nn + nA], pzA = x1[2 * Nn + nA];
    const float pxB = x1[nB], pyB = x1[Nn + nB], pzB = x1[2 * Nn + nB];
    const float pxC = x1[nC], pyC = x1[Nn + nC], pzC = x1[2 * Nn + nC];
    const float pxD = x1[nD], pyD = x1[Nn + nD], pzD = x1[2 * Nn + nD];

    const u64 px01 = pack2(pxA, pxB), py01 = pack2(pyA, pyB), pz01 = pack2(pzA, pzB);
    const u64 px23 = pack2(pxC, pxD), py23 = pack2(pyC, pyD), pz23 = pack2(pzC, pzD);

    float d0A = FLT_MAX, d1A = FLT_MAX, d2A = FLT_MAX;
    float d0B = FLT_MAX, d1B = FLT_MAX, d2B = FLT_MAX;
    float d0C = FLT_MAX, d1C = FLT_MAX, d2C = FLT_MAX;
    float d0D = FLT_MAX, d1D = FLT_MAX, d2D = FLT_MAX;
    int i0A = 0, i1A = 0, i2A = 0, i0B = 0, i1B = 0, i2B = 0;
    int i0C = 0, i1C = 0, i2C = 0, i0D = 0, i1D = 0, i2D = 0;

#pragma unroll 2
    for (int s = 0; s < SCHUNK; s++) {
        const ulonglong2 qa = qtab[s].a;
        const ulonglong2 qb = qtab[s].b;
        u64 e01 = ffma2(pz01, qb.x, qb.y);
        u64 e23 = ffma2(pz23, qb.x, qb.y);
        e01 = ffma2(py01, qa.y, e01);
        e23 = ffma2(py23, qa.y, e23);
        e01 = ffma2(px01, qa.x, e01);
        e23 = ffma2(px23, qa.x, e23);
        float eA, eB, eC, eD;
        unpack2(e01, eA, eB);
        unpack2(e23, eC, eD);

        if ((eA < d2A) | (eB < d2B) | (eC < d2C) | (eD < d2D)) {
            const int gs = sb + s;
            if (eA < d2A) {
                if (eA < d0A)      { d2A = d1A; i2A = i1A; d1A = d0A; i1A = i0A; d0A = eA; i0A = gs; }
                else if (eA < d1A) { d2A = d1A; i2A = i1A; d1A = eA;  i1A = gs; }
                else               { d2A = eA;  i2A = gs; }
            }
            if (eB < d2B) {
                if (eB < d0B)      { d2B = d1B; i2B = i1B; d1B = d0B; i1B = i0B; d0B = eB; i0B = gs; }
                else if (eB < d1B) { d2B = d1B; i2B = i1B; d1B = eB;  i1B = gs; }
                else               { d2B = eB;  i2B = gs; }
            }
            if (eC < d2C) {
                if (eC < d0C)      { d2C = d1C; i2C = i1C; d1C = d0C; i1C = i0C; d0C = eC; i0C = gs; }
                else if (eC < d1C) { d2C = d1C; i2C = i1C; d1C = eC;  i1C = gs; }
                else               { d2C = eC;  i2C = gs; }
            }
            if (eD < d2D) {
                if (eD < d0D)      { d2D = d1D; i2D = i1D; d1D = d0D; i1D = i0D; d0D = eD; i0D = gs; }
                else if (eD < d1D) { d2D = d1D; i2D = i1D; d1D = eD;  i1D = gs; }
                else               { d2D = eD;  i2D = gs; }
            }
        }
    }

    const int baseA = ((sp * Bn + b) * Nn + nA) * 3;
    g_pd[baseA + 0] = d0A; g_pd[baseA + 1] = d1A; g_pd[baseA + 2] = d2A;
    g_pi[baseA + 0] = i0A; g_pi[baseA + 1] = i1A; g_pi[baseA + 2] = i2A;
    const int baseB = ((sp * Bn + b) * Nn + nB) * 3;
    g_pd[baseB + 0] = d0B; g_pd[baseB + 1] = d1B; g_pd[baseB + 2] = d2B;
    g_pi[baseB + 0] = i0B; g_pi[baseB + 1] = i1B; g_pi[baseB + 2] = i2B;
    const int baseC = ((sp * Bn + b) * Nn + nC) * 3;
    g_pd[baseC + 0] = d0C; g_pd[baseC + 1] = d1C; g_pd[baseC + 2] = d2C;
    g_pi[baseC + 0] = i0C; g_pi[baseC + 1] = i1C; g_pi[baseC + 2] = i2C;
    const int baseD = ((sp * Bn + b) * Nn + nD) * 3;
    g_pd[baseD + 0] = d0D; g_pd[baseD + 1] = d1D; g_pd[baseD + 2] = d2D;
    g_pi[baseD + 0] = i0D; g_pi[baseD + 1] = i1D; g_pi[baseD + 2] = i2D;
}

// ---------------------------------------------------------------------------
// K2b: merge SPLITS sorted triples per point, compute interp weights.
// Split order == index order; strict < preserves top_k tie-break.
// ---------------------------------------------------------------------------
__global__ __launch_bounds__(256) void k2_merge(const float* __restrict__ xyz1) {
    const int t = blockIdx.x * 256 + threadIdx.x;
    const int b = t >> 14;
    const int n = t & (Nn - 1);

    float d0 = FLT_MAX, d1 = FLT_MAX, d2 = FLT_MAX;
    int   i0 = 0, i1 = 0, i2 = 0;

#pragma unroll
    for (int sp = 0; sp < SPLITS; sp++) {
        const int base = ((sp * Bn + b) * Nn + n) * 3;
#pragma unroll
        for (int r = 0; r < 3; r++) {
            const float e  = g_pd[base + r];
            const int   id = g_pi[base + r];
            if (e < d2) {
                if (e < d0)      { d2 = d1; i2 = i1; d1 = d0; i1 = i0; d0 = e; i0 = id; }
                else if (e < d1) { d2 = d1; i2 = i1; d1 = e;  i1 = id; }
                else             { d2 = e;  i2 = id; }
            }
        }
    }

    const float* x1 = xyz1 + b * 3 * Nn;
    const float px = x1[n], py = x1[Nn + n], pz = x1[2 * Nn + n];
    const float pn = px * px + py * py + pz * pz;
    const float r0 = 1.f / (d0 + pn + 1e-8f);
    const float r1 = 1.f / (d1 + pn + 1e-8f);
    const float r2 = 1.f / (d2 + pn + 1e-8f);
    const float inv = 1.f / (r0 + r1 + r2);

    const int base = (b * Nn + n) * 3;
    g_w[base + 0] = r0 * inv;
    g_w[base + 1] = r1 * inv;
    g_w[base + 2] = r2 * inv;
    g_i[base + 0] = i0;
    g_i[base + 1] = i1;
    g_i[base + 2] = i2;
}

// ---------------------------------------------------------------------------
// K3: gather + weighted sum + transpose-write.
// 256 threads = 4 point-groups x 64 lanes; float4 loads (4 channels/lane)
// -> 4x MLP and 4x fewer load instructions vs scalar version.
// ---------------------------------------------------------------------------
#define ACC_PITCH 261

__global__ __launch_bounds__(256) void k3_gather(float* __restrict__ out) {
    extern __shared__ unsigned char smem_raw[];
    float* acc = (float*)smem_raw;            // [64][ACC_PITCH]
    __shared__ float sw[64 * 3];
    __shared__ int   si[64 * 3];

    const int b   = blockIdx.y;
    const int n0  = blockIdx.x * 64;
    const int tid = threadIdx.x;

    for (int t = tid; t < 64 * 3; t += 256) {
        sw[t] = g_w[(b * Nn + n0) * 3 + t];
        si[t] = g_i[(b * Nn + n0) * 3 + t];
    }
    __syncthreads();

    const float* Gb = g_G + b * Sn * Cout;
    const int grp = tid >> 6;        // 0..3
    const int lane = tid & 63;       // 0..63 -> channels 4*lane..4*lane+3

#pragma unroll 2
    for (int p = grp; p < 64; p += 4) {
        const float w0 = sw[3 * p + 0];
        const float w1 = sw[3 * p + 1];
        const float w2 = sw[3 * p + 2];
        const int   j0 = si[3 * p + 0];
        const int   j1 = si[3 * p + 1];
        const int   j2 = si[3 * p + 2];
        const float4 a0 = *((const float4*)(Gb + j0 * Cout) + lane);
        const float4 a1 = *((const float4*)(Gb + j1 * Cout) + lane);
        const float4 a2 = *((const float4*)(Gb + j2 * Cout) + lane);
        float4 v;
        v.x = fmaf(w2, a2.x, fmaf(w1, a1.x, w0 * a0.x));
        v.y = fmaf(w2, a2.y, fmaf(w1, a1.y, w0 * a0.y));
        v.z = fmaf(w2, a2.z, fmaf(w1, a1.z, w0 * a0.z));
        v.w = fmaf(w2, a2.w, fmaf(w1, a1.w, w0 * a0.w));
        float* d = &acc[p * ACC_PITCH + 4 * lane];
        d[0] = v.x; d[1] = v.y; d[2] = v.z; d[3] = v.w;
    }
    __syncthreads();

    float* ob = out + b * Cout * Nn;
    for (int idx = tid; idx < 256 * 16; idx += 256) {
        const int c = idx >> 4;
        const int g = idx & 15;
        float4 v;
        v.x = acc[(4 * g + 0) * ACC_PITCH + c];
        v.y = acc[(4 * g + 1) * ACC_PITCH + c];
        v.z = acc[(4 * g + 2) * ACC_PITCH + c];
        v.w = acc[(4 * g + 3) * ACC_PITCH + c];
        *(float4*)&ob[c * Nn + n0 + 4 * g] = v;
    }
}

// ---------------------------------------------------------------------------
extern "C" void kernel_launch(void* const* d_in, const int* in_sizes, int n_in,
                              void* d_out, int out_size) {
    const float* xyz1 = (const float*)d_in[0];   // [B,3,N]
    const float* xyz2 = (const float*)d_in[1];   // [B,3,S]
    const float* P    = (const float*)d_in[2];   // [B,Cin,S]
    const float* W    = (const float*)d_in[3];   // [Cout,Cin]
    const float* bias = (const float*)d_in[4];   // [Cout]
    float* out = (float*)d_out;                  // [B,Cout,N]

    cudaFuncSetAttribute(k3_gather, cudaFuncAttributeMaxDynamicSharedMemorySize,
                         64 * ACC_PITCH * (int)sizeof(float));

    k1_gemm<<<dim3(Sn / 128, Cout / 128, Bn), 256>>>(P, W, bias);
    k2_partial<<<dim3(Nn / 1024, SPLITS, Bn), 256>>>(xyz1, xyz2);
    k2_merge<<<(Bn * Nn) / 256, 256>>>(xyz1);
    k3_gather<<<dim3(Nn / 64, Bn), 256, 64 * ACC_PITCH * sizeof(float)>>>(out);
}